// round 15
// baseline (speedup 1.0000x reference)
#include <cuda_runtime.h>
#include <cuda_fp16.h>
#include <cstdint>

#define HID 2048
#define NH 32
#define NKV 8
#define HD 64
#define NB 2
#define NT 2048
#define NTOK (NB * NT)   // 4096
#define QKVN 3072        // 2048 q + 512 k + 512 v
#define KOFF 2048
#define VOFF 2560

// ---------------------------------------------------------------------------
// Device-global scratch (no cudaMalloc allowed)
// ---------------------------------------------------------------------------
__device__ __half g_xh[(size_t)NTOK * HID];
__device__ __half g_wqkvT[(size_t)QKVN * HID];
__device__ __half g_woT[(size_t)HID * (NH * HD)];
__device__ __half g_qkvh[(size_t)NTOK * QKVN];
__device__ __half g_yh[(size_t)NTOK * NH * HD];

__device__ __forceinline__ void mma16816(float* c, const uint32_t* a,
                                         uint32_t b0, uint32_t b1) {
    asm volatile(
        "mma.sync.aligned.m16n8k16.row.col.f32.f16.f16.f32 "
        "{%0, %1, %2, %3}, {%4, %5, %6, %7}, {%8, %9}, {%0, %1, %2, %3};"
        : "+f"(c[0]), "+f"(c[1]), "+f"(c[2]), "+f"(c[3])
        : "r"(a[0]), "r"(a[1]), "r"(a[2]), "r"(a[3]), "r"(b0), "r"(b1));
}

__device__ __forceinline__ void ldsm_x4(uint32_t* r, uint32_t addr) {
    asm volatile(
        "ldmatrix.sync.aligned.m8n8.x4.shared.b16 {%0, %1, %2, %3}, [%4];"
        : "=r"(r[0]), "=r"(r[1]), "=r"(r[2]), "=r"(r[3]) : "r"(addr));
}

__device__ __forceinline__ void ldsm_x4_t(uint32_t* r, uint32_t addr) {
    asm volatile(
        "ldmatrix.sync.aligned.m8n8.x4.trans.shared.b16 {%0, %1, %2, %3}, [%4];"
        : "=r"(r[0]), "=r"(r[1]), "=r"(r[2]), "=r"(r[3]) : "r"(addr));
}

__device__ __forceinline__ uint32_t smem_u32(const void* p) {
    uint32_t r;
    asm("{ .reg .u64 t; cvta.to.shared.u64 t, %1; cvt.u32.u64 %0, t; }"
        : "=r"(r) : "l"(p));
    return r;
}

__device__ __forceinline__ void cp_async16(uint32_t dst, const void* src) {
    asm volatile("cp.async.cg.shared.global [%0], [%1], 16;" :: "r"(dst), "l"(src));
}
#define CP_COMMIT() asm volatile("cp.async.commit_group;" ::: "memory")
#define CP_WAIT0()  asm volatile("cp.async.wait_group 0;" ::: "memory")
#define CP_WAIT1()  asm volatile("cp.async.wait_group 1;" ::: "memory")

__device__ __forceinline__ uint32_t h2pack(float a, float b) {
    __half2 h = __floats2half2_rn(a, b);
    return *reinterpret_cast<uint32_t*>(&h);
}

// 0.125 * log2(e): q pre-scaled by this in the QKV GEMM epilogue
#define SC2 0.18033688011112042f

// ---------------------------------------------------------------------------
// Fused prologue: x -> fp16 copy AND all 4 weight transpose+converts.
// ---------------------------------------------------------------------------
__global__ void cvt_all(const float* __restrict__ x,
                        const float* __restrict__ Wq, const float* __restrict__ Wk,
                        const float* __restrict__ Wv, const float* __restrict__ Wo,
                        __half* __restrict__ xh,
                        __half* __restrict__ wqkvT, __half* __restrict__ woT)
{
    int bid = blockIdx.x;
    const int tid = threadIdx.y * 32 + threadIdx.x;

    if (bid < 8192) {
        size_t i = ((size_t)bid * 256 + tid) * 4;
        float4 v = *(const float4*)(x + i);
        uint2 o;
        o.x = h2pack(v.x, v.y);
        o.y = h2pack(v.z, v.w);
        *(uint2*)(xh + i) = o;
        return;
    }
    bid -= 8192;

    __shared__ float t[32][33];
    const float* src;
    __half* dst;
    int R, C, off;
    if (bid < 4096)      { src = Wq; dst = wqkvT; R = HID;     C = 2048; off = 0; }
    else if (bid < 5120) { bid -= 4096; src = Wk; dst = wqkvT; R = HID; C = 512; off = KOFF; }
    else if (bid < 6144) { bid -= 5120; src = Wv; dst = wqkvT; R = HID; C = 512; off = VOFF; }
    else                 { bid -= 6144; src = Wo; dst = woT;   R = NH * HD; C = HID; off = 0; }
    const int tilesX = C / 32;
    const int bx = bid % tilesX, by = bid / tilesX;

    int xx = bx * 32 + threadIdx.x;
    int y0 = by * 32;
#pragma unroll
    for (int j = 0; j < 32; j += 8)
        t[threadIdx.y + j][threadIdx.x] = src[(size_t)(y0 + threadIdx.y + j) * C + xx];
    __syncthreads();
    int xo = by * 32 + threadIdx.x;
#pragma unroll
    for (int j = 0; j < 32; j += 8)
        dst[(size_t)(off + bx * 32 + threadIdx.y + j) * R + xo] =
            __float2half_rn(t[threadIdx.x][threadIdx.y + j]);
}

// ---------------------------------------------------------------------------
// FP16 mma.sync GEMM, software-pipelined ldmatrix (ping-pong fragments),
// cp.async 3-stage, BK=64. Block 128x128x64, 256 thr, warp tile 64x32.
// ---------------------------------------------------------------------------
#define BM 128
#define BN 128
#define BK 64
#define GP 36
#define ASTG (BM * GP)
#define STGW (2 * ASTG)
#define NSTG 3
#define GEMM_SMEM_BYTES (NSTG * STGW * 4)

__global__ __launch_bounds__(256, 2) void gemm_h(const __half* __restrict__ A,
                                                 const __half* __restrict__ BT,
                                                 void* __restrict__ C,
                                                 int M, int N, int K, int out_half)
{
    extern __shared__ uint32_t sm[];
    const uint32_t smb = smem_u32(sm);

    const int tid = threadIdx.x;
    const int wid = tid >> 5;
    const int lid = tid & 31;
    const int gid = lid >> 2;
    const int tig = lid & 3;
    const int wm = wid & 1;
    const int wn = wid >> 1;

    const int a_row = (lid & 7) + ((lid & 8) ? 8 : 0);
    const int a_col = (lid & 16) ? 4 : 0;
    const int b_row = (lid & 7) + ((lid & 16) ? 8 : 0);
    const int b_col = (lid & 8) ? 4 : 0;

    const __half* Ag = A + (size_t)blockIdx.y * BM * K;
    const __half* Bg = BT + (size_t)blockIdx.x * BN * K;

    float acc[4][4][4];
#pragma unroll
    for (int mi = 0; mi < 4; mi++)
#pragma unroll
        for (int ni = 0; ni < 4; ni++)
#pragma unroll
            for (int r = 0; r < 4; r++) acc[mi][ni][r] = 0.f;

    const int nst = K / BK;

    auto stage_copy = [&](int s) {
        const uint32_t ab = smb + (uint32_t)((s % NSTG) * STGW) * 4;
        const uint32_t bb = ab + ASTG * 4;
#pragma unroll
        for (int t = 0; t < 4; t++) {
            int i = tid + t * 256;
            int r = i >> 3, j = i & 7;
            cp_async16(ab + (uint32_t)(r * GP + 4 * j) * 4,
                       Ag + (size_t)r * K + s * BK + 8 * j);
        }
#pragma unroll
        for (int t = 0; t < 4; t++) {
            int i = tid + t * 256;
            int r = i >> 3, j = i & 7;
            cp_async16(bb + (uint32_t)(r * GP + 4 * j) * 4,
                       Bg + (size_t)r * K + s * BK + 8 * j);
        }
    };

    stage_copy(0); CP_COMMIT();
    stage_copy(1); CP_COMMIT();

    for (int s = 0; s < nst; s++) {
        CP_WAIT1();
        __syncthreads();

        if (s + 2 < nst) stage_copy(s + 2);
        CP_COMMIT();

        const uint32_t ab = smb + (uint32_t)((s % NSTG) * STGW) * 4;
        const uint32_t bb = ab + ASTG * 4;
        const uint32_t aBase = ab + (uint32_t)((wm * 64 + a_row) * GP + a_col) * 4;
        const uint32_t bBase = bb + (uint32_t)((wn * 32 + b_row) * GP + b_col) * 4;

        uint32_t af[2][4][4], bf[2][2][4];
        // prime kk=0
#pragma unroll
        for (int mi = 0; mi < 4; mi++)
            ldsm_x4(af[0][mi], aBase + (uint32_t)(mi * 16 * GP) * 4);
#pragma unroll
        for (int p = 0; p < 2; p++)
            ldsm_x4(bf[0][p], bBase + (uint32_t)(p * 16 * GP) * 4);

#pragma unroll
        for (int kk = 0; kk < 4; kk++) {
            const int cur = kk & 1, nxt = cur ^ 1;
            if (kk < 3) {
                const uint32_t ko = (uint32_t)((kk + 1) * 8) * 4;
#pragma unroll
                for (int mi = 0; mi < 4; mi++)
                    ldsm_x4(af[nxt][mi], aBase + (uint32_t)(mi * 16 * GP) * 4 + ko);
#pragma unroll
                for (int p = 0; p < 2; p++)
                    ldsm_x4(bf[nxt][p], bBase + (uint32_t)(p * 16 * GP) * 4 + ko);
            }
#pragma unroll
            for (int mi = 0; mi < 4; mi++)
#pragma unroll
                for (int ni = 0; ni < 4; ni++) {
                    const int p = ni >> 1, ix = (ni & 1) * 2;
                    mma16816(acc[mi][ni], af[cur][mi], bf[cur][p][ix], bf[cur][p][ix + 1]);
                }
        }
    }

    const float sc = (out_half && (blockIdx.x * BN) < KOFF) ? SC2 : 1.f;

#pragma unroll
    for (int mi = 0; mi < 4; mi++) {
        int row = wm * 64 + mi * 16 + gid;
#pragma unroll
        for (int ni = 0; ni < 4; ni++) {
            int col = wn * 32 + ni * 8 + 2 * tig;
            if (out_half) {
                __half* Cp = (__half*)C + (size_t)blockIdx.y * BM * N + blockIdx.x * BN;
                *(uint32_t*)(Cp + (size_t)row * N + col) =
                    h2pack(acc[mi][ni][0] * sc, acc[mi][ni][1] * sc);
                *(uint32_t*)(Cp + (size_t)(row + 8) * N + col) =
                    h2pack(acc[mi][ni][2] * sc, acc[mi][ni][3] * sc);
            } else {
                float* Cp = (float*)C + (size_t)blockIdx.y * BM * N + blockIdx.x * BN;
                *(float2*)(Cp + (size_t)row * N + col) =
                    make_float2(acc[mi][ni][0], acc[mi][ni][1]);
                *(float2*)(Cp + (size_t)(row + 8) * N + col) =
                    make_float2(acc[mi][ni][2], acc[mi][ni][3]);
            }
        }
    }
}

// ---------------------------------------------------------------------------
// Flash attention: fp16 mma.sync, ping-pong ldmatrix pipelining in both
// S and PV phases, cp.async double-buffered K/V, max-free exp2 softmax,
// q pre-scaled, l deferred.
// ---------------------------------------------------------------------------
#define KTW (64 * 36)
#define FLASH_SMEM_BYTES (4 * KTW * 4)    // 36864 B

__global__ __launch_bounds__(128, 2) void flash_h(const __half* __restrict__ qkv,
                                                  __half* __restrict__ y)
{
    extern __shared__ uint32_t fsm[];
    const uint32_t smb = smem_u32(fsm);

    const int tid = threadIdx.x;
    const int wid = tid >> 5;
    const int lid = tid & 31;
    const int gid = lid >> 2;
    const int tig = lid & 3;

    const int b_row = (lid & 7) + ((lid & 16) ? 8 : 0);
    const int b_col = (lid & 8) ? 4 : 0;
    const int v_row = (lid & 7) + ((lid & 8) ? 8 : 0);
    const int v_col = (lid & 16) ? 4 : 0;

    const int bh = blockIdx.y;
    const int b = bh >> 5;
    const int h = bh & 31;
    const int hk = h >> 2;
    const int qb = blockIdx.x;
    const int qbase = qb * 128 + wid * 32;
    int qr0[2], qr1[2];
#pragma unroll
    for (int mi = 0; mi < 2; mi++) {
        qr0[mi] = qbase + mi * 16 + gid;
        qr1[mi] = qr0[mi] + 8;
    }

    const uint32_t* qkvw = (const uint32_t*)qkv;

    auto load_kv = [&](int kt, int st) {
        const uint32_t kb = smb + (uint32_t)(st * 2 * KTW) * 4;
        const uint32_t vb = kb + KTW * 4;
#pragma unroll
        for (int t = 0; t < 4; t++) {
            int i = tid + t * 128;
            int r = i >> 3, c = i & 7;
            const uint32_t* rowp = qkvw + (size_t)(b * NT + kt * 64 + r) * (QKVN / 2)
                                   + hk * (HD / 2) + 4 * c;
            cp_async16(kb + (uint32_t)(r * 36 + 4 * c) * 4, rowp + (KOFF / 2));
            cp_async16(vb + (uint32_t)(r * 36 + 4 * c) * 4, rowp + (VOFF / 2));
        }
    };

    // Q fragments (pre-scaled by SC2; direct word loads from global, once)
    uint32_t qa[2][4][4];
#pragma unroll
    for (int mi = 0; mi < 2; mi++) {
        const uint32_t* q0 = qkvw + (size_t)(b * NT + qr0[mi]) * (QKVN / 2) + h * (HD / 2);
        const uint32_t* q1 = qkvw + (size_t)(b * NT + qr1[mi]) * (QKVN / 2) + h * (HD / 2);
#pragma unroll
        for (int ks = 0; ks < 4; ks++) {
            qa[mi][ks][0] = q0[ks * 8 + tig];
            qa[mi][ks][1] = q1[ks * 8 + tig];
            qa[mi][ks][2] = q0[ks * 8 + tig + 4];
            qa[mi][ks][3] = q1[ks * 8 + tig + 4];
        }
    }

    float oacc[2][8][4];
#pragma unroll
    for (int mi = 0; mi < 2; mi++)
#pragma unroll
        for (int nb = 0; nb < 8; nb++)
#pragma unroll
            for (int r = 0; r < 4; r++) oacc[mi][nb][r] = 0.f;
    float lsum[2][2] = { { 0.f, 0.f }, { 0.f, 0.f } };

    const int ntiles = 2 * qb + 2;

    load_kv(0, 0); CP_COMMIT();

    for (int kt = 0; kt < ntiles; kt++) {
        const int st = kt & 1;
        CP_WAIT0();
        __syncthreads();

        if (kt + 1 < ntiles) { load_kv(kt + 1, st ^ 1); }
        CP_COMMIT();

        const uint32_t ksB = smb + (uint32_t)(st * 2 * KTW) * 4;
        const uint32_t vsB = ksB + KTW * 4;
        const uint32_t kLane = ksB + (uint32_t)(b_row * 36 + b_col) * 4;
        const uint32_t vLane = vsB + (uint32_t)(v_row * 36 + v_col) * 4;

        if (kt * 64 > qbase + 31) continue;

        // ---- S = Q K^T (pipelined K fragment loads) ----
        float sacc[2][8][4];
#pragma unroll
        for (int mi = 0; mi < 2; mi++)
#pragma unroll
            for (int nb = 0; nb < 8; nb++)
#pragma unroll
                for (int r = 0; r < 4; r++) sacc[mi][nb][r] = 0.f;

        {
            uint32_t kf[2][4][4];
#pragma unroll
            for (int p = 0; p < 4; p++)
                ldsm_x4(kf[0][p], kLane + (uint32_t)(p * 16 * 36) * 4);
#pragma unroll
            for (int ks = 0; ks < 4; ks++) {
                const int cur = ks & 1, nxt = cur ^ 1;
                if (ks < 3) {
#pragma unroll
                    for (int p = 0; p < 4; p++)
                        ldsm_x4(kf[nxt][p],
                                kLane + (uint32_t)(p * 16 * 36 + (ks + 1) * 8) * 4);
                }
#pragma unroll
                for (int p = 0; p < 4; p++) {
                    mma16816(sacc[0][2 * p],     qa[0][ks], kf[cur][p][0], kf[cur][p][1]);
                    mma16816(sacc[1][2 * p],     qa[1][ks], kf[cur][p][0], kf[cur][p][1]);
                    mma16816(sacc[0][2 * p + 1], qa[0][ks], kf[cur][p][2], kf[cur][p][3]);
                    mma16816(sacc[1][2 * p + 1], qa[1][ks], kf[cur][p][2], kf[cur][p][3]);
                }
            }
        }

        // ---- max-free softmax: mask (diag only), exp2, pack to A-frags ----
        uint32_t pareg[2][4][4];
#pragma unroll
        for (int mi = 0; mi < 2; mi++) {
            const bool dg = (kt * 64 + 63) > qr0[mi];
#pragma unroll
            for (int nb = 0; nb < 8; nb++) {
                float s0 = sacc[mi][nb][0];
                float s1 = sacc[mi][nb][1];
                float s2 = sacc[mi][nb][2];
                float s3 = sacc[mi][nb][3];
                if (dg) {
                    int key0 = kt * 64 + nb * 8 + 2 * tig;
                    if (key0 > qr0[mi])     s0 = -1e30f;
                    if (key0 + 1 > qr0[mi]) s1 = -1e30f;
                    if (key0 > qr1[mi])     s2 = -1e30f;
                    if (key0 + 1 > qr1[mi]) s3 = -1e30f;
                }
                float p0 = exp2f(s0);
                float p1 = exp2f(s1);
                float p2 = exp2f(s2);
                float p3 = exp2f(s3);
                lsum[mi][0] += p0 + p1;
                lsum[mi][1] += p2 + p3;
                pareg[mi][nb >> 1][(nb & 1) * 2 + 0] = h2pack(p0, p1);
                pareg[mi][nb >> 1][(nb & 1) * 2 + 1] = h2pack(p2, p3);
            }
        }

        // ---- O += P V (pipelined V fragment loads) ----
        {
            uint32_t vf[2][4][4];
#pragma unroll
            for (int p = 0; p < 4; p++)
                ldsm_x4_t(vf[0][p], vLane + (uint32_t)(p * 8) * 4);
#pragma unroll
            for (int ks = 0; ks < 4; ks++) {
                const int cur = ks & 1, nxt = cur ^ 1;
                if (ks < 3) {
#pragma unroll
                    for (int p = 0; p < 4; p++)
                        ldsm_x4_t(vf[nxt][p],
                                  vLane + (uint32_t)((ks + 1) * 16 * 36 + p * 8) * 4);
                }
#pragma unroll
                for (int p = 0; p < 4; p++) {
                    mma16816(oacc[0][2 * p],     pareg[0][ks], vf[cur][p][0], vf[cur][p][1]);
                    mma16816(oacc[1][2 * p],     pareg[1][ks], vf[cur][p][0], vf[cur][p][1]);
                    mma16816(oacc[0][2 * p + 1], pareg[0][ks], vf[cur][p][2], vf[cur][p][3]);
                    mma16816(oacc[1][2 * p + 1], pareg[1][ks], vf[cur][p][2], vf[cur][p][3]);
                }
            }
        }
    }

    // ---- epilogue: deferred l reduction, then y fp16 ----
#pragma unroll
    for (int mi = 0; mi < 2; mi++) {
        float l0 = lsum[mi][0], l1 = lsum[mi][1];
        l0 += __shfl_xor_sync(0xffffffffu, l0, 1);
        l0 += __shfl_xor_sync(0xffffffffu, l0, 2);
        l1 += __shfl_xor_sync(0xffffffffu, l1, 1);
        l1 += __shfl_xor_sync(0xffffffffu, l1, 2);
        float il0 = 1.f / l0, il1 = 1.f / l1;
        __half* y0 = y + ((size_t)(b * NT + qr0[mi]) * NH + h) * HD;
        __half* y1 = y + ((size_t)(b * NT + qr1[mi]) * NH + h) * HD;
#pragma unroll
        for (int nb = 0; nb < 8; nb++) {
            int col = nb * 8 + 2 * tig;
            *(uint32_t*)(y0 + col) = h2pack(oacc[mi][nb][0] * il0, oacc[mi][nb][1] * il0);
            *(uint32_t*)(y1 + col) = h2pack(oacc[mi][nb][2] * il1, oacc[mi][nb][3] * il1);
        }
    }
}

// ---------------------------------------------------------------------------
// Launch
// ---------------------------------------------------------------------------
extern "C" void kernel_launch(void* const* d_in, const int* in_sizes, int n_in,
                              void* d_out, int out_size)
{
    const float* x  = (const float*)d_in[0];
    const float* Wq = (const float*)d_in[2];
    const float* Wk = (const float*)d_in[3];
    const float* Wv = (const float*)d_in[4];
    const float* Wo = (const float*)d_in[5];
    float* out = (float*)d_out;

    __half *xh, *wqkvT, *woT, *qkvh, *yh;
    cudaGetSymbolAddress((void**)&xh, g_xh);
    cudaGetSymbolAddress((void**)&wqkvT, g_wqkvT);
    cudaGetSymbolAddress((void**)&woT, g_woT);
    cudaGetSymbolAddress((void**)&qkvh, g_qkvh);
    cudaGetSymbolAddress((void**)&yh, g_yh);

    cudaFuncSetAttribute(gemm_h, cudaFuncAttributeMaxDynamicSharedMemorySize,
                         GEMM_SMEM_BYTES);
    cudaFuncSetAttribute(flash_h, cudaFuncAttributeMaxDynamicSharedMemorySize,
                         FLASH_SMEM_BYTES);

    dim3 tb(32, 8);
    cvt_all<<<18432, tb>>>(x, Wq, Wk, Wv, Wo, xh, wqkvT, woT);

    gemm_h<<<dim3(QKVN / BN, NTOK / BM), 256, GEMM_SMEM_BYTES>>>(
        xh, wqkvT, qkvh, NTOK, QKVN, HID, 1);

    flash_h<<<dim3(NT / 128, NB * NH), 128, FLASH_SMEM_BYTES>>>(qkvh, yh);

    gemm_h<<<dim3(HID / BN, NTOK / BM), 256, GEMM_SMEM_BYTES>>>(
        yh, woT, out, NTOK, NH * HD, HID, 0);
}

// round 16
// speedup vs baseline: 1.0323x; 1.0323x over previous
#include <cuda_runtime.h>
#include <cuda_fp16.h>
#include <cstdint>

#define HID 2048
#define NH 32
#define NKV 8
#define HD 64
#define NB 2
#define NT 2048
#define NTOK (NB * NT)   // 4096
#define QKVN 3072        // 2048 q + 512 k + 512 v
#define KOFF 2048
#define VOFF 2560

// ---------------------------------------------------------------------------
// Device-global scratch (no cudaMalloc allowed)
// ---------------------------------------------------------------------------
__device__ __half g_xh[(size_t)NTOK * HID];
__device__ __half g_wqkvT[(size_t)QKVN * HID];
__device__ __half g_woT[(size_t)HID * (NH * HD)];
__device__ __half g_qkvh[(size_t)NTOK * QKVN];
__device__ __half g_yh[(size_t)NTOK * NH * HD];

__device__ __forceinline__ void mma16816(float* c, const uint32_t* a,
                                         uint32_t b0, uint32_t b1) {
    asm volatile(
        "mma.sync.aligned.m16n8k16.row.col.f32.f16.f16.f32 "
        "{%0, %1, %2, %3}, {%4, %5, %6, %7}, {%8, %9}, {%0, %1, %2, %3};"
        : "+f"(c[0]), "+f"(c[1]), "+f"(c[2]), "+f"(c[3])
        : "r"(a[0]), "r"(a[1]), "r"(a[2]), "r"(a[3]), "r"(b0), "r"(b1));
}

__device__ __forceinline__ void ldsm_x4(uint32_t* r, uint32_t addr) {
    asm volatile(
        "ldmatrix.sync.aligned.m8n8.x4.shared.b16 {%0, %1, %2, %3}, [%4];"
        : "=r"(r[0]), "=r"(r[1]), "=r"(r[2]), "=r"(r[3]) : "r"(addr));
}

__device__ __forceinline__ void ldsm_x4_t(uint32_t* r, uint32_t addr) {
    asm volatile(
        "ldmatrix.sync.aligned.m8n8.x4.trans.shared.b16 {%0, %1, %2, %3}, [%4];"
        : "=r"(r[0]), "=r"(r[1]), "=r"(r[2]), "=r"(r[3]) : "r"(addr));
}

__device__ __forceinline__ uint32_t smem_u32(const void* p) {
    uint32_t r;
    asm("{ .reg .u64 t; cvta.to.shared.u64 t, %1; cvt.u32.u64 %0, t; }"
        : "=r"(r) : "l"(p));
    return r;
}

__device__ __forceinline__ void cp_async16(uint32_t dst, const void* src) {
    asm volatile("cp.async.cg.shared.global [%0], [%1], 16;" :: "r"(dst), "l"(src));
}
#define CP_COMMIT() asm volatile("cp.async.commit_group;" ::: "memory")
#define CP_WAIT0()  asm volatile("cp.async.wait_group 0;" ::: "memory")
#define CP_WAIT1()  asm volatile("cp.async.wait_group 1;" ::: "memory")

__device__ __forceinline__ uint32_t h2pack(float a, float b) {
    __half2 h = __floats2half2_rn(a, b);
    return *reinterpret_cast<uint32_t*>(&h);
}

// 0.125 * log2(e): q pre-scaled by this in the QKV GEMM epilogue
#define SC2 0.18033688011112042f
#define ONES_H2 0x3C003C00u   // packed fp16 {1.0, 1.0}

// ---------------------------------------------------------------------------
// Fused prologue: x -> fp16 copy AND all 4 weight transpose+converts.
// ---------------------------------------------------------------------------
__global__ void cvt_all(const float* __restrict__ x,
                        const float* __restrict__ Wq, const float* __restrict__ Wk,
                        const float* __restrict__ Wv, const float* __restrict__ Wo,
                        __half* __restrict__ xh,
                        __half* __restrict__ wqkvT, __half* __restrict__ woT)
{
    int bid = blockIdx.x;
    const int tid = threadIdx.y * 32 + threadIdx.x;

    if (bid < 8192) {
        size_t i = ((size_t)bid * 256 + tid) * 4;
        float4 v = *(const float4*)(x + i);
        uint2 o;
        o.x = h2pack(v.x, v.y);
        o.y = h2pack(v.z, v.w);
        *(uint2*)(xh + i) = o;
        return;
    }
    bid -= 8192;

    __shared__ float t[32][33];
    const float* src;
    __half* dst;
    int R, C, off;
    if (bid < 4096)      { src = Wq; dst = wqkvT; R = HID;     C = 2048; off = 0; }
    else if (bid < 5120) { bid -= 4096; src = Wk; dst = wqkvT; R = HID; C = 512; off = KOFF; }
    else if (bid < 6144) { bid -= 5120; src = Wv; dst = wqkvT; R = HID; C = 512; off = VOFF; }
    else                 { bid -= 6144; src = Wo; dst = woT;   R = NH * HD; C = HID; off = 0; }
    const int tilesX = C / 32;
    const int bx = bid % tilesX, by = bid / tilesX;

    int xx = bx * 32 + threadIdx.x;
    int y0 = by * 32;
#pragma unroll
    for (int j = 0; j < 32; j += 8)
        t[threadIdx.y + j][threadIdx.x] = src[(size_t)(y0 + threadIdx.y + j) * C + xx];
    __syncthreads();
    int xo = by * 32 + threadIdx.x;
#pragma unroll
    for (int j = 0; j < 32; j += 8)
        dst[(size_t)(off + bx * 32 + threadIdx.y + j) * R + xo] =
            __float2half_rn(t[threadIdx.x][threadIdx.y + j]);
}

// ---------------------------------------------------------------------------
// FP16 mma.sync GEMM, ldmatrix fragments, cp.async 3-stage, BK=64.
// (R14 structure — flat fragment loads; manual ping-pong regressed.)
// ---------------------------------------------------------------------------
#define BM 128
#define BN 128
#define BK 64
#define GP 36
#define ASTG (BM * GP)
#define STGW (2 * ASTG)
#define NSTG 3
#define GEMM_SMEM_BYTES (NSTG * STGW * 4)

__global__ __launch_bounds__(256, 2) void gemm_h(const __half* __restrict__ A,
                                                 const __half* __restrict__ BT,
                                                 void* __restrict__ C,
                                                 int M, int N, int K, int out_half)
{
    extern __shared__ uint32_t sm[];
    const uint32_t smb = smem_u32(sm);

    const int tid = threadIdx.x;
    const int wid = tid >> 5;
    const int lid = tid & 31;
    const int gid = lid >> 2;
    const int tig = lid & 3;
    const int wm = wid & 1;
    const int wn = wid >> 1;

    const int a_row = (lid & 7) + ((lid & 8) ? 8 : 0);
    const int a_col = (lid & 16) ? 4 : 0;
    const int b_row = (lid & 7) + ((lid & 16) ? 8 : 0);
    const int b_col = (lid & 8) ? 4 : 0;

    const __half* Ag = A + (size_t)blockIdx.y * BM * K;
    const __half* Bg = BT + (size_t)blockIdx.x * BN * K;

    float acc[4][4][4];
#pragma unroll
    for (int mi = 0; mi < 4; mi++)
#pragma unroll
        for (int ni = 0; ni < 4; ni++)
#pragma unroll
            for (int r = 0; r < 4; r++) acc[mi][ni][r] = 0.f;

    const int nst = K / BK;

    auto stage_copy = [&](int s) {
        const uint32_t ab = smb + (uint32_t)((s % NSTG) * STGW) * 4;
        const uint32_t bb = ab + ASTG * 4;
#pragma unroll
        for (int t = 0; t < 4; t++) {
            int i = tid + t * 256;
            int r = i >> 3, j = i & 7;
            cp_async16(ab + (uint32_t)(r * GP + 4 * j) * 4,
                       Ag + (size_t)r * K + s * BK + 8 * j);
        }
#pragma unroll
        for (int t = 0; t < 4; t++) {
            int i = tid + t * 256;
            int r = i >> 3, j = i & 7;
            cp_async16(bb + (uint32_t)(r * GP + 4 * j) * 4,
                       Bg + (size_t)r * K + s * BK + 8 * j);
        }
    };

    stage_copy(0); CP_COMMIT();
    stage_copy(1); CP_COMMIT();

    for (int s = 0; s < nst; s++) {
        CP_WAIT1();
        __syncthreads();

        if (s + 2 < nst) stage_copy(s + 2);
        CP_COMMIT();

        const uint32_t ab = smb + (uint32_t)((s % NSTG) * STGW) * 4;
        const uint32_t bb = ab + ASTG * 4;
        const uint32_t aBase = ab + (uint32_t)((wm * 64 + a_row) * GP + a_col) * 4;
        const uint32_t bBase = bb + (uint32_t)((wn * 32 + b_row) * GP + b_col) * 4;

#pragma unroll
        for (int kk = 0; kk < 4; kk++) {
            const uint32_t ko = (uint32_t)(kk * 8) * 4;
            uint32_t af[4][4], bf2[2][4];
#pragma unroll
            for (int mi = 0; mi < 4; mi++)
                ldsm_x4(af[mi], aBase + (uint32_t)(mi * 16 * GP) * 4 + ko);
#pragma unroll
            for (int p = 0; p < 2; p++)
                ldsm_x4(bf2[p], bBase + (uint32_t)(p * 16 * GP) * 4 + ko);
#pragma unroll
            for (int mi = 0; mi < 4; mi++)
#pragma unroll
                for (int ni = 0; ni < 4; ni++) {
                    const int p = ni >> 1, ix = (ni & 1) * 2;
                    mma16816(acc[mi][ni], af[mi], bf2[p][ix], bf2[p][ix + 1]);
                }
        }
    }

    const float sc = (out_half && (blockIdx.x * BN) < KOFF) ? SC2 : 1.f;

#pragma unroll
    for (int mi = 0; mi < 4; mi++) {
        int row = wm * 64 + mi * 16 + gid;
#pragma unroll
        for (int ni = 0; ni < 4; ni++) {
            int col = wn * 32 + ni * 8 + 2 * tig;
            if (out_half) {
                __half* Cp = (__half*)C + (size_t)blockIdx.y * BM * N + blockIdx.x * BN;
                *(uint32_t*)(Cp + (size_t)row * N + col) =
                    h2pack(acc[mi][ni][0] * sc, acc[mi][ni][1] * sc);
                *(uint32_t*)(Cp + (size_t)(row + 8) * N + col) =
                    h2pack(acc[mi][ni][2] * sc, acc[mi][ni][3] * sc);
            } else {
                float* Cp = (float*)C + (size_t)blockIdx.y * BM * N + blockIdx.x * BN;
                *(float2*)(Cp + (size_t)row * N + col) =
                    make_float2(acc[mi][ni][0], acc[mi][ni][1]);
                *(float2*)(Cp + (size_t)(row + 8) * N + col) =
                    make_float2(acc[mi][ni][2], acc[mi][ni][3]);
            }
        }
    }
}

// ---------------------------------------------------------------------------
// Flash attention: fp16 mma.sync + ldmatrix, cp.async double-buffered K/V,
// max-free exp2 softmax (q pre-scaled), P in registers.
// NEW: l computed by ones-vector MMA (l = P @ 1) fused into the PV loop —
// replaces 64 scalar FADDs/tile and the epilogue shfl reduction.
// ---------------------------------------------------------------------------
#define KTW (64 * 36)
#define FLASH_SMEM_BYTES (4 * KTW * 4)    // 36864 B

__global__ __launch_bounds__(128, 2) void flash_h(const __half* __restrict__ qkv,
                                                  __half* __restrict__ y)
{
    extern __shared__ uint32_t fsm[];
    const uint32_t smb = smem_u32(fsm);

    const int tid = threadIdx.x;
    const int wid = tid >> 5;
    const int lid = tid & 31;
    const int gid = lid >> 2;
    const int tig = lid & 3;

    const int b_row = (lid & 7) + ((lid & 16) ? 8 : 0);
    const int b_col = (lid & 8) ? 4 : 0;
    const int v_row = (lid & 7) + ((lid & 8) ? 8 : 0);
    const int v_col = (lid & 16) ? 4 : 0;

    const int bh = blockIdx.y;
    const int b = bh >> 5;
    const int h = bh & 31;
    const int hk = h >> 2;
    const int qb = blockIdx.x;
    const int qbase = qb * 128 + wid * 32;
    int qr0[2], qr1[2];
#pragma unroll
    for (int mi = 0; mi < 2; mi++) {
        qr0[mi] = qbase + mi * 16 + gid;
        qr1[mi] = qr0[mi] + 8;
    }

    const uint32_t* qkvw = (const uint32_t*)qkv;

    auto load_kv = [&](int kt, int st) {
        const uint32_t kb = smb + (uint32_t)(st * 2 * KTW) * 4;
        const uint32_t vb = kb + KTW * 4;
#pragma unroll
        for (int t = 0; t < 4; t++) {
            int i = tid + t * 128;
            int r = i >> 3, c = i & 7;
            const uint32_t* rowp = qkvw + (size_t)(b * NT + kt * 64 + r) * (QKVN / 2)
                                   + hk * (HD / 2) + 4 * c;
            cp_async16(kb + (uint32_t)(r * 36 + 4 * c) * 4, rowp + (KOFF / 2));
            cp_async16(vb + (uint32_t)(r * 36 + 4 * c) * 4, rowp + (VOFF / 2));
        }
    };

    // Q fragments (pre-scaled by SC2; direct word loads from global, once)
    uint32_t qa[2][4][4];
#pragma unroll
    for (int mi = 0; mi < 2; mi++) {
        const uint32_t* q0 = qkvw + (size_t)(b * NT + qr0[mi]) * (QKVN / 2) + h * (HD / 2);
        const uint32_t* q1 = qkvw + (size_t)(b * NT + qr1[mi]) * (QKVN / 2) + h * (HD / 2);
#pragma unroll
        for (int ks = 0; ks < 4; ks++) {
            qa[mi][ks][0] = q0[ks * 8 + tig];
            qa[mi][ks][1] = q1[ks * 8 + tig];
            qa[mi][ks][2] = q0[ks * 8 + tig + 4];
            qa[mi][ks][3] = q1[ks * 8 + tig + 4];
        }
    }

    float oacc[2][8][4];
#pragma unroll
    for (int mi = 0; mi < 2; mi++)
#pragma unroll
        for (int nb = 0; nb < 8; nb++)
#pragma unroll
            for (int r = 0; r < 4; r++) oacc[mi][nb][r] = 0.f;
    float lacc[2][4];
#pragma unroll
    for (int mi = 0; mi < 2; mi++)
#pragma unroll
        for (int r = 0; r < 4; r++) lacc[mi][r] = 0.f;

    const int ntiles = 2 * qb + 2;

    load_kv(0, 0); CP_COMMIT();

    for (int kt = 0; kt < ntiles; kt++) {
        const int st = kt & 1;
        CP_WAIT0();
        __syncthreads();

        if (kt + 1 < ntiles) { load_kv(kt + 1, st ^ 1); }
        CP_COMMIT();

        const uint32_t ksB = smb + (uint32_t)(st * 2 * KTW) * 4;
        const uint32_t vsB = ksB + KTW * 4;
        const uint32_t kLane = ksB + (uint32_t)(b_row * 36 + b_col) * 4;
        const uint32_t vLane = vsB + (uint32_t)(v_row * 36 + v_col) * 4;

        if (kt * 64 > qbase + 31) continue;

        // ---- S = Q K^T (already in exp2 domain) ----
        float sacc[2][8][4];
#pragma unroll
        for (int mi = 0; mi < 2; mi++)
#pragma unroll
            for (int nb = 0; nb < 8; nb++)
#pragma unroll
                for (int r = 0; r < 4; r++) sacc[mi][nb][r] = 0.f;

#pragma unroll
        for (int ks = 0; ks < 4; ks++) {
            uint32_t kf[4][4];
#pragma unroll
            for (int p = 0; p < 4; p++)
                ldsm_x4(kf[p], kLane + (uint32_t)(p * 16 * 36 + ks * 8) * 4);
#pragma unroll
            for (int p = 0; p < 4; p++) {
                mma16816(sacc[0][2 * p],     qa[0][ks], kf[p][0], kf[p][1]);
                mma16816(sacc[1][2 * p],     qa[1][ks], kf[p][0], kf[p][1]);
                mma16816(sacc[0][2 * p + 1], qa[0][ks], kf[p][2], kf[p][3]);
                mma16816(sacc[1][2 * p + 1], qa[1][ks], kf[p][2], kf[p][3]);
            }
        }

        // ---- max-free softmax: mask (diag only), exp2, pack to A-frags ----
        uint32_t pareg[2][4][4];
#pragma unroll
        for (int mi = 0; mi < 2; mi++) {
            const bool dg = (kt * 64 + 63) > qr0[mi];
#pragma unroll
            for (int nb = 0; nb < 8; nb++) {
                float s0 = sacc[mi][nb][0];
                float s1 = sacc[mi][nb][1];
                float s2 = sacc[mi][nb][2];
                float s3 = sacc[mi][nb][3];
                if (dg) {
                    int key0 = kt * 64 + nb * 8 + 2 * tig;
                    if (key0 > qr0[mi])     s0 = -1e30f;
                    if (key0 + 1 > qr0[mi]) s1 = -1e30f;
                    if (key0 > qr1[mi])     s2 = -1e30f;
                    if (key0 + 1 > qr1[mi]) s3 = -1e30f;
                }
                float p0 = exp2f(s0);
                float p1 = exp2f(s1);
                float p2 = exp2f(s2);
                float p3 = exp2f(s3);
                pareg[mi][nb >> 1][(nb & 1) * 2 + 0] = h2pack(p0, p1);
                pareg[mi][nb >> 1][(nb & 1) * 2 + 1] = h2pack(p2, p3);
            }
        }

        // ---- O += P V ;  l += P @ 1  (fused ones-vector MMA) ----
#pragma unroll
        for (int ks = 0; ks < 4; ks++) {
            uint32_t vf[4][4];
#pragma unroll
            for (int p = 0; p < 4; p++)
                ldsm_x4_t(vf[p], vLane + (uint32_t)(ks * 16 * 36 + p * 8) * 4);
#pragma unroll
            for (int p = 0; p < 4; p++) {
                mma16816(oacc[0][2 * p],     pareg[0][ks], vf[p][0], vf[p][1]);
                mma16816(oacc[1][2 * p],     pareg[1][ks], vf[p][0], vf[p][1]);
                mma16816(oacc[0][2 * p + 1], pareg[0][ks], vf[p][2], vf[p][3]);
                mma16816(oacc[1][2 * p + 1], pareg[1][ks], vf[p][2], vf[p][3]);
            }
            mma16816(lacc[0], pareg[0][ks], ONES_H2, ONES_H2);
            mma16816(lacc[1], pareg[1][ks], ONES_H2, ONES_H2);
        }
    }

    // ---- epilogue: l comes straight from lacc (all ones-columns equal) ----
#pragma unroll
    for (int mi = 0; mi < 2; mi++) {
        float il0 = 1.f / lacc[mi][0];
        float il1 = 1.f / lacc[mi][2];
        __half* y0 = y + ((size_t)(b * NT + qr0[mi]) * NH + h) * HD;
        __half* y1 = y + ((size_t)(b * NT + qr1[mi]) * NH + h) * HD;
#pragma unroll
        for (int nb = 0; nb < 8; nb++) {
            int col = nb * 8 + 2 * tig;
            *(uint32_t*)(y0 + col) = h2pack(oacc[mi][nb][0] * il0, oacc[mi][nb][1] * il0);
            *(uint32_t*)(y1 + col) = h2pack(oacc[mi][nb][2] * il1, oacc[mi][nb][3] * il1);
        }
    }
}

// ---------------------------------------------------------------------------
// Launch
// ---------------------------------------------------------------------------
extern "C" void kernel_launch(void* const* d_in, const int* in_sizes, int n_in,
                              void* d_out, int out_size)
{
    const float* x  = (const float*)d_in[0];
    const float* Wq = (const float*)d_in[2];
    const float* Wk = (const float*)d_in[3];
    const float* Wv = (const float*)d_in[4];
    const float* Wo = (const float*)d_in[5];
    float* out = (float*)d_out;

    __half *xh, *wqkvT, *woT, *qkvh, *yh;
    cudaGetSymbolAddress((void**)&xh, g_xh);
    cudaGetSymbolAddress((void**)&wqkvT, g_wqkvT);
    cudaGetSymbolAddress((void**)&woT, g_woT);
    cudaGetSymbolAddress((void**)&qkvh, g_qkvh);
    cudaGetSymbolAddress((void**)&yh, g_yh);

    cudaFuncSetAttribute(gemm_h, cudaFuncAttributeMaxDynamicSharedMemorySize,
                         GEMM_SMEM_BYTES);
    cudaFuncSetAttribute(flash_h, cudaFuncAttributeMaxDynamicSharedMemorySize,
                         FLASH_SMEM_BYTES);

    dim3 tb(32, 8);
    cvt_all<<<18432, tb>>>(x, Wq, Wk, Wv, Wo, xh, wqkvT, woT);

    gemm_h<<<dim3(QKVN / BN, NTOK / BM), 256, GEMM_SMEM_BYTES>>>(
        xh, wqkvT, qkvh, NTOK, QKVN, HID, 1);

    flash_h<<<dim3(NT / 128, NB * NH), 128, FLASH_SMEM_BYTES>>>(qkvh, yh);

    gemm_h<<<dim3(HID / BN, NTOK / BM), 256, GEMM_SMEM_BYTES>>>(
        yh, woT, out, NTOK, NH * HD, HID, 0);
}

// round 17
// speedup vs baseline: 1.0358x; 1.0034x over previous
#include <cuda_runtime.h>
#include <cuda_fp16.h>
#include <cstdint>

#define HID 2048
#define NH 32
#define NKV 8
#define HD 64
#define NB 2
#define NT 2048
#define NTOK (NB * NT)   // 4096
#define QKVN 3072        // 2048 q + 512 k + 512 v
#define KOFF 2048
#define VOFF 2560

// ---------------------------------------------------------------------------
// Device-global scratch (no cudaMalloc allowed)
// ---------------------------------------------------------------------------
__device__ __half g_xh[(size_t)NTOK * HID];
__device__ __half g_wqkvT[(size_t)QKVN * HID];
__device__ __half g_woT[(size_t)HID * (NH * HD)];
__device__ __half g_qkvh[(size_t)NTOK * QKVN];
__device__ __half g_yh[(size_t)NTOK * NH * HD];

__device__ __forceinline__ void mma16816(float* c, const uint32_t* a,
                                         uint32_t b0, uint32_t b1) {
    asm volatile(
        "mma.sync.aligned.m16n8k16.row.col.f32.f16.f16.f32 "
        "{%0, %1, %2, %3}, {%4, %5, %6, %7}, {%8, %9}, {%0, %1, %2, %3};"
        : "+f"(c[0]), "+f"(c[1]), "+f"(c[2]), "+f"(c[3])
        : "r"(a[0]), "r"(a[1]), "r"(a[2]), "r"(a[3]), "r"(b0), "r"(b1));
}

__device__ __forceinline__ void ldsm_x4(uint32_t* r, uint32_t addr) {
    asm volatile(
        "ldmatrix.sync.aligned.m8n8.x4.shared.b16 {%0, %1, %2, %3}, [%4];"
        : "=r"(r[0]), "=r"(r[1]), "=r"(r[2]), "=r"(r[3]) : "r"(addr));
}

__device__ __forceinline__ void ldsm_x4_t(uint32_t* r, uint32_t addr) {
    asm volatile(
        "ldmatrix.sync.aligned.m8n8.x4.trans.shared.b16 {%0, %1, %2, %3}, [%4];"
        : "=r"(r[0]), "=r"(r[1]), "=r"(r[2]), "=r"(r[3]) : "r"(addr));
}

__device__ __forceinline__ uint32_t smem_u32(const void* p) {
    uint32_t r;
    asm("{ .reg .u64 t; cvta.to.shared.u64 t, %1; cvt.u32.u64 %0, t; }"
        : "=r"(r) : "l"(p));
    return r;
}

__device__ __forceinline__ void cp_async16(uint32_t dst, const void* src) {
    asm volatile("cp.async.cg.shared.global [%0], [%1], 16;" :: "r"(dst), "l"(src));
}
#define CP_COMMIT() asm volatile("cp.async.commit_group;" ::: "memory")
#define CP_WAIT0()  asm volatile("cp.async.wait_group 0;" ::: "memory")
#define CP_WAIT1()  asm volatile("cp.async.wait_group 1;" ::: "memory")

__device__ __forceinline__ uint32_t h2pack(float a, float b) {
    __half2 h = __floats2half2_rn(a, b);
    return *reinterpret_cast<uint32_t*>(&h);
}

// 0.125 * log2(e): q pre-scaled by this in the QKV GEMM epilogue
#define SC2 0.18033688011112042f
#define ONES_H2 0x3C003C00u   // packed fp16 {1.0, 1.0}

// ---------------------------------------------------------------------------
// Fused prologue: x -> fp16 copy AND all 4 weight transpose+converts.
// ---------------------------------------------------------------------------
__global__ void cvt_all(const float* __restrict__ x,
                        const float* __restrict__ Wq, const float* __restrict__ Wk,
                        const float* __restrict__ Wv, const float* __restrict__ Wo,
                        __half* __restrict__ xh,
                        __half* __restrict__ wqkvT, __half* __restrict__ woT)
{
    int bid = blockIdx.x;
    const int tid = threadIdx.y * 32 + threadIdx.x;

    if (bid < 8192) {
        size_t i = ((size_t)bid * 256 + tid) * 4;
        float4 v = *(const float4*)(x + i);
        uint2 o;
        o.x = h2pack(v.x, v.y);
        o.y = h2pack(v.z, v.w);
        *(uint2*)(xh + i) = o;
        return;
    }
    bid -= 8192;

    __shared__ float t[32][33];
    const float* src;
    __half* dst;
    int R, C, off;
    if (bid < 4096)      { src = Wq; dst = wqkvT; R = HID;     C = 2048; off = 0; }
    else if (bid < 5120) { bid -= 4096; src = Wk; dst = wqkvT; R = HID; C = 512; off = KOFF; }
    else if (bid < 6144) { bid -= 5120; src = Wv; dst = wqkvT; R = HID; C = 512; off = VOFF; }
    else                 { bid -= 6144; src = Wo; dst = woT;   R = NH * HD; C = HID; off = 0; }
    const int tilesX = C / 32;
    const int bx = bid % tilesX, by = bid / tilesX;

    int xx = bx * 32 + threadIdx.x;
    int y0 = by * 32;
#pragma unroll
    for (int j = 0; j < 32; j += 8)
        t[threadIdx.y + j][threadIdx.x] = src[(size_t)(y0 + threadIdx.y + j) * C + xx];
    __syncthreads();
    int xo = by * 32 + threadIdx.x;
#pragma unroll
    for (int j = 0; j < 32; j += 8)
        dst[(size_t)(off + bx * 32 + threadIdx.y + j) * R + xo] =
            __float2half_rn(t[threadIdx.x][threadIdx.y + j]);
}

// ---------------------------------------------------------------------------
// FP16 mma.sync GEMM, ldmatrix fragments, cp.async 3-stage, BK=64. (unchanged)
// ---------------------------------------------------------------------------
#define BM 128
#define BN 128
#define BK 64
#define GP 36
#define ASTG (BM * GP)
#define STGW (2 * ASTG)
#define NSTG 3
#define GEMM_SMEM_BYTES (NSTG * STGW * 4)

__global__ __launch_bounds__(256, 2) void gemm_h(const __half* __restrict__ A,
                                                 const __half* __restrict__ BT,
                                                 void* __restrict__ C,
                                                 int M, int N, int K, int out_half)
{
    extern __shared__ uint32_t sm[];
    const uint32_t smb = smem_u32(sm);

    const int tid = threadIdx.x;
    const int wid = tid >> 5;
    const int lid = tid & 31;
    const int gid = lid >> 2;
    const int tig = lid & 3;
    const int wm = wid & 1;
    const int wn = wid >> 1;

    const int a_row = (lid & 7) + ((lid & 8) ? 8 : 0);
    const int a_col = (lid & 16) ? 4 : 0;
    const int b_row = (lid & 7) + ((lid & 16) ? 8 : 0);
    const int b_col = (lid & 8) ? 4 : 0;

    const __half* Ag = A + (size_t)blockIdx.y * BM * K;
    const __half* Bg = BT + (size_t)blockIdx.x * BN * K;

    float acc[4][4][4];
#pragma unroll
    for (int mi = 0; mi < 4; mi++)
#pragma unroll
        for (int ni = 0; ni < 4; ni++)
#pragma unroll
            for (int r = 0; r < 4; r++) acc[mi][ni][r] = 0.f;

    const int nst = K / BK;

    auto stage_copy = [&](int s) {
        const uint32_t ab = smb + (uint32_t)((s % NSTG) * STGW) * 4;
        const uint32_t bb = ab + ASTG * 4;
#pragma unroll
        for (int t = 0; t < 4; t++) {
            int i = tid + t * 256;
            int r = i >> 3, j = i & 7;
            cp_async16(ab + (uint32_t)(r * GP + 4 * j) * 4,
                       Ag + (size_t)r * K + s * BK + 8 * j);
        }
#pragma unroll
        for (int t = 0; t < 4; t++) {
            int i = tid + t * 256;
            int r = i >> 3, j = i & 7;
            cp_async16(bb + (uint32_t)(r * GP + 4 * j) * 4,
                       Bg + (size_t)r * K + s * BK + 8 * j);
        }
    };

    stage_copy(0); CP_COMMIT();
    stage_copy(1); CP_COMMIT();

    for (int s = 0; s < nst; s++) {
        CP_WAIT1();
        __syncthreads();

        if (s + 2 < nst) stage_copy(s + 2);
        CP_COMMIT();

        const uint32_t ab = smb + (uint32_t)((s % NSTG) * STGW) * 4;
        const uint32_t bb = ab + ASTG * 4;
        const uint32_t aBase = ab + (uint32_t)((wm * 64 + a_row) * GP + a_col) * 4;
        const uint32_t bBase = bb + (uint32_t)((wn * 32 + b_row) * GP + b_col) * 4;

#pragma unroll
        for (int kk = 0; kk < 4; kk++) {
            const uint32_t ko = (uint32_t)(kk * 8) * 4;
            uint32_t af[4][4], bf2[2][4];
#pragma unroll
            for (int mi = 0; mi < 4; mi++)
                ldsm_x4(af[mi], aBase + (uint32_t)(mi * 16 * GP) * 4 + ko);
#pragma unroll
            for (int p = 0; p < 2; p++)
                ldsm_x4(bf2[p], bBase + (uint32_t)(p * 16 * GP) * 4 + ko);
#pragma unroll
            for (int mi = 0; mi < 4; mi++)
#pragma unroll
                for (int ni = 0; ni < 4; ni++) {
                    const int p = ni >> 1, ix = (ni & 1) * 2;
                    mma16816(acc[mi][ni], af[mi], bf2[p][ix], bf2[p][ix + 1]);
                }
        }
    }

    const float sc = (out_half && (blockIdx.x * BN) < KOFF) ? SC2 : 1.f;

#pragma unroll
    for (int mi = 0; mi < 4; mi++) {
        int row = wm * 64 + mi * 16 + gid;
#pragma unroll
        for (int ni = 0; ni < 4; ni++) {
            int col = wn * 32 + ni * 8 + 2 * tig;
            if (out_half) {
                __half* Cp = (__half*)C + (size_t)blockIdx.y * BM * N + blockIdx.x * BN;
                *(uint32_t*)(Cp + (size_t)row * N + col) =
                    h2pack(acc[mi][ni][0] * sc, acc[mi][ni][1] * sc);
                *(uint32_t*)(Cp + (size_t)(row + 8) * N + col) =
                    h2pack(acc[mi][ni][2] * sc, acc[mi][ni][3] * sc);
            } else {
                float* Cp = (float*)C + (size_t)blockIdx.y * BM * N + blockIdx.x * BN;
                *(float2*)(Cp + (size_t)row * N + col) =
                    make_float2(acc[mi][ni][0], acc[mi][ni][1]);
                *(float2*)(Cp + (size_t)(row + 8) * N + col) =
                    make_float2(acc[mi][ni][2], acc[mi][ni][3]);
            }
        }
    }
}

// ---------------------------------------------------------------------------
// Flash attention: 128 thr / 4 warps, 16 q-rows per warp (64 per block),
// 4 BLOCKS/SM (regs clamped to 128) -> 4 warps/SMSP so softmax overlaps
// other warps' HMMA. Max-free exp2 softmax (q pre-scaled), P in registers,
// l via ones-MMA, V via ldmatrix.trans, cp.async double-buffered K/V.
// ---------------------------------------------------------------------------
#define KTW (64 * 36)
#define FLASH_SMEM_BYTES (4 * KTW * 4)    // 36864 B

__global__ __launch_bounds__(128, 4) void flash_h(const __half* __restrict__ qkv,
                                                  __half* __restrict__ y)
{
    extern __shared__ uint32_t fsm[];
    const uint32_t smb = smem_u32(fsm);

    const int tid = threadIdx.x;
    const int wid = tid >> 5;
    const int lid = tid & 31;
    const int gid = lid >> 2;
    const int tig = lid & 3;

    const int b_row = (lid & 7) + ((lid & 16) ? 8 : 0);
    const int b_col = (lid & 8) ? 4 : 0;
    const int v_row = (lid & 7) + ((lid & 8) ? 8 : 0);
    const int v_col = (lid & 16) ? 4 : 0;

    const int bh = blockIdx.y;
    const int b = bh >> 5;
    const int h = bh & 31;
    const int hk = h >> 2;
    const int qb = blockIdx.x;                 // 0..31 (64 q-rows per block)
    const int qbase = qb * 64 + wid * 16;
    const int qr0 = qbase + gid;
    const int qr1 = qr0 + 8;

    const uint32_t* qkvw = (const uint32_t*)qkv;

    auto load_kv = [&](int kt, int st) {
        const uint32_t kb = smb + (uint32_t)(st * 2 * KTW) * 4;
        const uint32_t vb = kb + KTW * 4;
#pragma unroll
        for (int t = 0; t < 4; t++) {
            int i = tid + t * 128;
            int r = i >> 3, c = i & 7;
            const uint32_t* rowp = qkvw + (size_t)(b * NT + kt * 64 + r) * (QKVN / 2)
                                   + hk * (HD / 2) + 4 * c;
            cp_async16(kb + (uint32_t)(r * 36 + 4 * c) * 4, rowp + (KOFF / 2));
            cp_async16(vb + (uint32_t)(r * 36 + 4 * c) * 4, rowp + (VOFF / 2));
        }
    };

    // Q fragments (pre-scaled by SC2)
    uint32_t qa[4][4];
    {
        const uint32_t* q0 = qkvw + (size_t)(b * NT + qr0) * (QKVN / 2) + h * (HD / 2);
        const uint32_t* q1 = qkvw + (size_t)(b * NT + qr1) * (QKVN / 2) + h * (HD / 2);
#pragma unroll
        for (int ks = 0; ks < 4; ks++) {
            qa[ks][0] = q0[ks * 8 + tig];
            qa[ks][1] = q1[ks * 8 + tig];
            qa[ks][2] = q0[ks * 8 + tig + 4];
            qa[ks][3] = q1[ks * 8 + tig + 4];
        }
    }

    float oacc[8][4];
#pragma unroll
    for (int nb = 0; nb < 8; nb++)
#pragma unroll
        for (int r = 0; r < 4; r++) oacc[nb][r] = 0.f;
    float lacc[4] = { 0.f, 0.f, 0.f, 0.f };

    const int ntiles = qb + 1;

    load_kv(0, 0); CP_COMMIT();

    for (int kt = 0; kt < ntiles; kt++) {
        const int st = kt & 1;
        CP_WAIT0();
        __syncthreads();

        if (kt + 1 < ntiles) { load_kv(kt + 1, st ^ 1); }
        CP_COMMIT();

        const uint32_t ksB = smb + (uint32_t)(st * 2 * KTW) * 4;
        const uint32_t vsB = ksB + KTW * 4;
        const uint32_t kLane = ksB + (uint32_t)(b_row * 36 + b_col) * 4;
        const uint32_t vLane = vsB + (uint32_t)(v_row * 36 + v_col) * 4;

        if (kt * 64 > qbase + 15) continue;   // fully masked for this warp

        // ---- S = Q K^T (exp2 domain) ----
        float sacc[8][4];
#pragma unroll
        for (int nb = 0; nb < 8; nb++)
#pragma unroll
            for (int r = 0; r < 4; r++) sacc[nb][r] = 0.f;

#pragma unroll
        for (int ks = 0; ks < 4; ks++) {
            uint32_t kf[4][4];
#pragma unroll
            for (int p = 0; p < 4; p++)
                ldsm_x4(kf[p], kLane + (uint32_t)(p * 16 * 36 + ks * 8) * 4);
#pragma unroll
            for (int p = 0; p < 4; p++) {
                mma16816(sacc[2 * p],     qa[ks], kf[p][0], kf[p][1]);
                mma16816(sacc[2 * p + 1], qa[ks], kf[p][2], kf[p][3]);
            }
        }

        // ---- max-free softmax: mask (diag only), exp2, pack to A-frags ----
        uint32_t pareg[4][4];
        {
            const bool dg = (kt * 64 + 63) > qr0;
#pragma unroll
            for (int nb = 0; nb < 8; nb++) {
                float s0 = sacc[nb][0];
                float s1 = sacc[nb][1];
                float s2 = sacc[nb][2];
                float s3 = sacc[nb][3];
                if (dg) {
                    int key0 = kt * 64 + nb * 8 + 2 * tig;
                    if (key0 > qr0)     s0 = -1e30f;
                    if (key0 + 1 > qr0) s1 = -1e30f;
                    if (key0 > qr1)     s2 = -1e30f;
                    if (key0 + 1 > qr1) s3 = -1e30f;
                }
                float p0 = exp2f(s0);
                float p1 = exp2f(s1);
                float p2 = exp2f(s2);
                float p3 = exp2f(s3);
                pareg[nb >> 1][(nb & 1) * 2 + 0] = h2pack(p0, p1);
                pareg[nb >> 1][(nb & 1) * 2 + 1] = h2pack(p2, p3);
            }
        }

        // ---- O += P V ;  l += P @ 1 ----
#pragma unroll
        for (int ks = 0; ks < 4; ks++) {
            uint32_t vf[4][4];
#pragma unroll
            for (int p = 0; p < 4; p++)
                ldsm_x4_t(vf[p], vLane + (uint32_t)(ks * 16 * 36 + p * 8) * 4);
#pragma unroll
            for (int p = 0; p < 4; p++) {
                mma16816(oacc[2 * p],     pareg[ks], vf[p][0], vf[p][1]);
                mma16816(oacc[2 * p + 1], pareg[ks], vf[p][2], vf[p][3]);
            }
            mma16816(lacc, pareg[ks], ONES_H2, ONES_H2);
        }
    }

    // ---- epilogue ----
    {
        float il0 = 1.f / lacc[0];
        float il1 = 1.f / lacc[2];
        __half* y0 = y + ((size_t)(b * NT + qr0) * NH + h) * HD;
        __half* y1 = y + ((size_t)(b * NT + qr1) * NH + h) * HD;
#pragma unroll
        for (int nb = 0; nb < 8; nb++) {
            int col = nb * 8 + 2 * tig;
            *(uint32_t*)(y0 + col) = h2pack(oacc[nb][0] * il0, oacc[nb][1] * il0);
            *(uint32_t*)(y1 + col) = h2pack(oacc[nb][2] * il1, oacc[nb][3] * il1);
        }
    }
}

// ---------------------------------------------------------------------------
// Launch
// ---------------------------------------------------------------------------
extern "C" void kernel_launch(void* const* d_in, const int* in_sizes, int n_in,
                              void* d_out, int out_size)
{
    const float* x  = (const float*)d_in[0];
    const float* Wq = (const float*)d_in[2];
    const float* Wk = (const float*)d_in[3];
    const float* Wv = (const float*)d_in[4];
    const float* Wo = (const float*)d_in[5];
    float* out = (float*)d_out;

    __half *xh, *wqkvT, *woT, *qkvh, *yh;
    cudaGetSymbolAddress((void**)&xh, g_xh);
    cudaGetSymbolAddress((void**)&wqkvT, g_wqkvT);
    cudaGetSymbolAddress((void**)&woT, g_woT);
    cudaGetSymbolAddress((void**)&qkvh, g_qkvh);
    cudaGetSymbolAddress((void**)&yh, g_yh);

    cudaFuncSetAttribute(gemm_h, cudaFuncAttributeMaxDynamicSharedMemorySize,
                         GEMM_SMEM_BYTES);
    cudaFuncSetAttribute(flash_h, cudaFuncAttributeMaxDynamicSharedMemorySize,
                         FLASH_SMEM_BYTES);

    dim3 tb(32, 8);
    cvt_all<<<18432, tb>>>(x, Wq, Wk, Wv, Wo, xh, wqkvT, woT);

    gemm_h<<<dim3(QKVN / BN, NTOK / BM), 256, GEMM_SMEM_BYTES>>>(
        xh, wqkvT, qkvh, NTOK, QKVN, HID, 1);

    flash_h<<<dim3(NT / 64, NB * NH), 128, FLASH_SMEM_BYTES>>>(qkvh, yh);

    gemm_h<<<dim3(HID / BN, NTOK / BM), 256, GEMM_SMEM_BYTES>>>(
        yh, woT, out, NTOK, NH * HD, HID, 0);
}